// round 9
// baseline (speedup 1.0000x reference)
#include <cuda_runtime.h>
#include <cuda_fp16.h>
#include <cstdint>
#include <cstddef>

#define TOK 16384
#define HD 1024
#define MD 2048
#define NE 16
#define RT (TOK*2)

// ---------------- scratch (device globals: allocation-free) ----------------
__device__ int    g_cnt[NE];
__device__ int    g_cur[NE];
__device__ int    g_offs[NE+1];
__device__ int    g_texp[RT];
__device__ float  g_tw[RT];
__device__ int    g_ptok[RT];
__device__ float  g_pw[RT];
__device__ int    g_pos[RT];
__device__ __half g_xah [(size_t)RT * HD];      // gathered A, fp16 (67MB)
__device__ __half g_w1h [(size_t)NE * HD * MD]; // W1 fp16, original [e][k][n] layout
__device__ __half g_w2h [(size_t)NE * MD * HD]; // W2 fp16, original [e][k][n] layout
__device__ __half g_hmidh[(size_t)RT * MD];     // intermediate, fp16 (134MB)
__device__ float  g_y   [(size_t)RT * HD];      // per-(token,expert) outputs fp32

// ---------------- helpers ----------------
__device__ __forceinline__ uint32_t smem_u32(const void* p){
    uint32_t a;
    asm("{ .reg .u64 t; cvta.to.shared.u64 t, %1; cvt.u32.u64 %0, t; }" : "=r"(a) : "l"(p));
    return a;
}
__device__ __forceinline__ void cpa16(uint32_t dst, const void* src, bool valid){
    asm volatile("cp.async.cg.shared.global [%0], [%1], 16, %2;\n"
                 :: "r"(dst), "l"(src), "r"(valid ? 16 : 0) : "memory");
}
__device__ __forceinline__ void ldsm4(uint32_t* r, uint32_t addr){
    asm volatile("ldmatrix.sync.aligned.m8n8.x4.shared.b16 {%0,%1,%2,%3}, [%4];"
                 : "=r"(r[0]), "=r"(r[1]), "=r"(r[2]), "=r"(r[3]) : "r"(addr));
}
__device__ __forceinline__ void ldsm4t(uint32_t* r, uint32_t addr){
    asm volatile("ldmatrix.sync.aligned.m8n8.x4.trans.shared.b16 {%0,%1,%2,%3}, [%4];"
                 : "=r"(r[0]), "=r"(r[1]), "=r"(r[2]), "=r"(r[3]) : "r"(addr));
}
__device__ __forceinline__ void mma_f16(float* c, const uint32_t* a, const uint32_t* b){
    asm volatile("mma.sync.aligned.m16n8k16.row.col.f32.f16.f16.f32 "
        "{%0,%1,%2,%3}, {%4,%5,%6,%7}, {%8,%9}, {%0,%1,%2,%3};"
        : "+f"(c[0]), "+f"(c[1]), "+f"(c[2]), "+f"(c[3])
        : "r"(a[0]), "r"(a[1]), "r"(a[2]), "r"(a[3]), "r"(b[0]), "r"(b[1]));
}

// ---------------- routing kernels ----------------
__global__ void init_kernel(){
    int i = threadIdx.x;
    if (i < NE){ g_cnt[i] = 0; g_cur[i] = 0; }
}

__global__ __launch_bounds__(256) void gate_kernel(const float* __restrict__ X,
        const float* __restrict__ Wg, const float* __restrict__ bg){
    int warp = threadIdx.x >> 5, lane = threadIdx.x & 31;
    int t = blockIdx.x * 8 + warp;
    float acc[NE];
    #pragma unroll
    for (int e = 0; e < NE; e++) acc[e] = 0.f;
    const float* xr = X + (size_t)t * HD;
    for (int h = lane; h < HD; h += 32){
        float x = xr[h];
        const float4* w4 = (const float4*)(Wg + (size_t)h * NE);
        #pragma unroll
        for (int j = 0; j < 4; j++){
            float4 w = w4[j];
            acc[4*j+0] += x * w.x; acc[4*j+1] += x * w.y;
            acc[4*j+2] += x * w.z; acc[4*j+3] += x * w.w;
        }
    }
    #pragma unroll
    for (int e = 0; e < NE; e++){
        #pragma unroll
        for (int off = 16; off; off >>= 1)
            acc[e] += __shfl_xor_sync(0xffffffffu, acc[e], off);
    }
    if (lane == 0){
        #pragma unroll
        for (int e = 0; e < NE; e++) acc[e] += bg[e];
        int i1 = 0;
        #pragma unroll
        for (int e = 1; e < NE; e++) if (acc[e] > acc[i1]) i1 = e;
        int i2 = (i1 == 0) ? 1 : 0;
        #pragma unroll
        for (int e = 0; e < NE; e++) if (e != i1 && acc[e] > acc[i2]) i2 = e;
        float w1 = 1.f / (1.f + expf(acc[i2] - acc[i1]));
        float w2 = 1.f - w1;
        g_texp[2*t]   = i1; g_tw[2*t]   = w1;
        g_texp[2*t+1] = i2; g_tw[2*t+1] = w2;
        atomicAdd(&g_cnt[i1], 1); atomicAdd(&g_cnt[i2], 1);
    }
}

__global__ void scan_kernel(){
    if (threadIdx.x == 0){
        int s = 0;
        for (int e = 0; e < NE; e++){ g_offs[e] = s; s += g_cnt[e]; }
        g_offs[NE] = s;
    }
}

__global__ __launch_bounds__(256) void scatter_kernel(){
    int i = blockIdx.x * 256 + threadIdx.x;
    int e = g_texp[i];
    int p = g_offs[e] + atomicAdd(&g_cur[e], 1);
    g_ptok[p] = i >> 1;
    g_pw[p]   = g_tw[i];
    g_pos[i]  = p;
}

// ---------------- pre-passes: fp32 -> fp16 ----------------
__global__ __launch_bounds__(256) void cvt_half_kernel(const float* __restrict__ src,
                                                       __half* __restrict__ dst){
    size_t i = (size_t)blockIdx.x * 256 + threadIdx.x;   // one float4 per thread
    float4 v = ((const float4*)src)[i];
    __half2* d2 = (__half2*)dst;
    d2[2*i]   = __floats2half2_rn(v.x, v.y);
    d2[2*i+1] = __floats2half2_rn(v.z, v.w);
}

__global__ __launch_bounds__(256) void gather_cvt(const float* __restrict__ X){
    int p = blockIdx.x;
    int t = g_ptok[p];
    float4 v = ((const float4*)(X + (size_t)t * HD))[threadIdx.x];
    __half2* d2 = (__half2*)(g_xah + (size_t)p * HD);
    d2[2*threadIdx.x]   = __floats2half2_rn(v.x, v.y);
    d2[2*threadIdx.x+1] = __floats2half2_rn(v.z, v.w);
}

// ---------------- fp16 grouped GEMM, BK=64, 3-stage cp.async pipeline -------
// PHASE 1: hmid[p,:] = f16(relu(xa[p,:] @ W1[e] + b1[e]))   (KD=HD, ND=MD)
// PHASE 2: y[p,:]    = pw(p) * (hmid[p,:] @ W2[e] + b2[e])  (KD=MD, ND=HD)
static constexpr int ASTRB = 144;    // bytes per A SMEM row (64 halves + 8 pad)
static constexpr int BSTRB = 528;    // bytes per B SMEM row (256 halves + 8 pad)
static constexpr int ABYTES = 128 * ASTRB;   // 18432
static constexpr int BBYTES = 64 * BSTRB;    // 33792
static constexpr int GEMM_SMEM = 1024 + 3 * (ABYTES + BBYTES);  // 157696

template<int KD, int ND, int PHASE>
__global__ __launch_bounds__(256, 1)
void moe_gemm_h(const float* __restrict__ bias)
{
    constexpr int BM = 128, BN = 256, BK = 64, S = 3;
    constexpr int NC = KD / BK;
    extern __shared__ char smem[];
    float* bias_s = (float*)smem;
    const uint32_t As0 = smem_u32(smem + 1024);
    const uint32_t Bs0 = As0 + S * ABYTES;

    const int e = blockIdx.z;
    const int start = g_offs[e];
    const int rows  = g_offs[e+1] - start;
    const int m0 = blockIdx.y * BM;
    if (m0 >= rows) return;
    const int n0 = blockIdx.x * BN;
    const int tid = threadIdx.x, wid = tid >> 5, lane = tid & 31;

    const __half* Ab = (PHASE == 1) ? (const __half*)g_xah : (const __half*)g_hmidh;
    const __half* Wh = (PHASE == 1) ? (const __half*)g_w1h : (const __half*)g_w2h;

    bias_s[tid] = bias[(size_t)e * ND + n0 + tid];

    // staging assignment
    const int ar = tid >> 1, ac = tid & 1;          // A: row, 64B-half of 128B row
    const bool a_ok = (m0 + ar) < rows;
    const __half* a_srcrow = Ab + (size_t)(start + m0 + (a_ok ? ar : 0)) * KD + ac * 32;
    const uint32_t a_doff = (uint32_t)(ar * ASTRB + ac * 64);
    const int br = tid >> 2, bc = tid & 3;          // B: k-row (0..63), 128B col chunk
    const __half* b_srcrow = Wh + ((size_t)e * KD + br) * ND + n0 + bc * 64;
    const uint32_t b_doff = (uint32_t)(br * BSTRB + bc * 128);

    auto stage = [&](int c, int slot){
        uint32_t Abase = As0 + slot * ABYTES;
        uint32_t Bbase = Bs0 + slot * BBYTES;
        const __half* as = a_srcrow + c * BK;
        #pragma unroll
        for (int j = 0; j < 4; j++) cpa16(Abase + a_doff + j*16, as + j*8, a_ok);
        const __half* bs = b_srcrow + (size_t)c * BK * ND;
        #pragma unroll
        for (int j = 0; j < 8; j++) cpa16(Bbase + b_doff + j*16, bs + j*8, true);
    };

    // prologue: stages 0..S-2
    #pragma unroll
    for (int i = 0; i < S-1; i++){
        stage(i, i);
        asm volatile("cp.async.commit_group;" ::: "memory");
    }

    // per-lane fragment addressing
    const int wm = (wid & 1) * 64, wn = (wid >> 1) * 64;
    const int g = lane >> 3, lr = lane & 7, gq = lane >> 2, tq = lane & 3;
    const uint32_t aoff = (uint32_t)((wm + (g & 1) * 8 + lr) * ASTRB + (g >> 1) * 16);
    const uint32_t boff = (uint32_t)(((g & 1) * 8 + lr) * BSTRB + (g >> 1) * 16 + wn * 2);

    float c[4][8][4];
    #pragma unroll
    for (int a = 0; a < 4; a++)
        #pragma unroll
        for (int b = 0; b < 8; b++)
            #pragma unroll
            for (int k = 0; k < 4; k++) c[a][b][k] = 0.f;

    int slot = 0;
    for (int i = 0; i < NC; i++){
        asm volatile("cp.async.wait_group %0;" :: "n"(S-2) : "memory");
        __syncthreads();
        {
            int ns = slot + (S - 1); if (ns >= S) ns -= S;
            if (i + S - 1 < NC) stage(i + S - 1, ns);
            asm volatile("cp.async.commit_group;" ::: "memory");
        }

        const uint32_t Abase = As0 + slot * ABYTES + aoff;
        const uint32_t Bbase = Bs0 + slot * BBYTES + boff;
        #pragma unroll
        for (int ks = 0; ks < 4; ks++){
            uint32_t af[4][4], bf[4][4];
            #pragma unroll
            for (int mt = 0; mt < 4; mt++)
                ldsm4(af[mt], Abase + mt * (16 * ASTRB) + ks * 32);
            #pragma unroll
            for (int nt = 0; nt < 4; nt++)
                ldsm4t(bf[nt], Bbase + ks * (16 * BSTRB) + nt * 32);
            #pragma unroll
            for (int mt = 0; mt < 4; mt++)
                #pragma unroll
                for (int nt = 0; nt < 4; nt++){
                    mma_f16(c[mt][2*nt],   af[mt], bf[nt]);
                    mma_f16(c[mt][2*nt+1], af[mt], bf[nt] + 2);
                }
        }
        if (++slot == S) slot = 0;
    }

    // ---------------- epilogue ----------------
    #pragma unroll
    for (int mt = 0; mt < 4; mt++){
        const int r0l = wm + mt * 16 + gq;
        const int r1l = r0l + 8;
        const bool v0 = (m0 + r0l) < rows;
        const bool v1 = (m0 + r1l) < rows;
        const size_t gr0 = (size_t)(start + m0 + (v0 ? r0l : 0));
        const size_t gr1 = (size_t)(start + m0 + (v1 ? r1l : 0));
        float pw0 = 0.f, pw1 = 0.f;
        if (PHASE == 2){
            pw0 = v0 ? g_pw[gr0] : 0.f;
            pw1 = v1 ? g_pw[gr1] : 0.f;
        }
        #pragma unroll
        for (int j = 0; j < 8; j++){
            const int nw = (j >> 1) * 16 + (j & 1) * 8;
            const int n = wn + nw + 2 * tq;
            const float bb0 = bias_s[n], bb1 = bias_s[n + 1];
            float v00 = c[mt][j][0] + bb0, v01 = c[mt][j][1] + bb1;
            float v10 = c[mt][j][2] + bb0, v11 = c[mt][j][3] + bb1;
            if (PHASE == 1){
                if (v0)
                    *(__half2*)(g_hmidh + gr0 * ND + n0 + n) =
                        __floats2half2_rn(fmaxf(v00, 0.f), fmaxf(v01, 0.f));
                if (v1)
                    *(__half2*)(g_hmidh + gr1 * ND + n0 + n) =
                        __floats2half2_rn(fmaxf(v10, 0.f), fmaxf(v11, 0.f));
            } else {
                if (v0)
                    *(float2*)(g_y + gr0 * ND + n0 + n) = make_float2(v00 * pw0, v01 * pw0);
                if (v1)
                    *(float2*)(g_y + gr1 * ND + n0 + n) = make_float2(v10 * pw1, v11 * pw1);
            }
        }
    }
}

// ---------------- combine: out[t] = Y[pos(t,0)] + Y[pos(t,1)] ----------------
__global__ __launch_bounds__(256) void combine_kernel(float* __restrict__ out){
    size_t idx = (size_t)blockIdx.x * 256 + threadIdx.x;
    int t = (int)(idx >> 8);
    int j = (int)(idx & 255);
    int p0 = g_pos[2 * t], p1 = g_pos[2 * t + 1];
    const float4* Y4 = (const float4*)g_y;
    float4 a = Y4[(size_t)p0 * (HD / 4) + j];
    float4 b = Y4[(size_t)p1 * (HD / 4) + j];
    ((float4*)out)[idx] = make_float4(a.x + b.x, a.y + b.y, a.z + b.z, a.w + b.w);
}

// ---------------- launch ----------------
extern "C" void kernel_launch(void* const* d_in, const int* in_sizes, int n_in,
                              void* d_out, int out_size) {
    const float* X  = (const float*)d_in[0];
    const float* Wg = (const float*)d_in[1];
    const float* bg = (const float*)d_in[2];
    const float* W1 = (const float*)d_in[3];
    const float* b1 = (const float*)d_in[4];
    const float* W2 = (const float*)d_in[5];
    const float* b2 = (const float*)d_in[6];
    float* out = (float*)d_out;

    // one-time resources (host-side only; created on the uncaptured correctness
    // call, reused by capture — capture sees only fork/join edges)
    static cudaStream_t s2 = nullptr;
    static cudaEvent_t evFork = nullptr, evW1 = nullptr, evW2 = nullptr;
    if (!s2){
        cudaStreamCreateWithFlags(&s2, cudaStreamNonBlocking);
        cudaEventCreateWithFlags(&evFork, cudaEventDisableTiming);
        cudaEventCreateWithFlags(&evW1,  cudaEventDisableTiming);
        cudaEventCreateWithFlags(&evW2,  cudaEventDisableTiming);
        cudaFuncSetAttribute(moe_gemm_h<HD, MD, 1>,
                             cudaFuncAttributeMaxDynamicSharedMemorySize, GEMM_SMEM);
        cudaFuncSetAttribute(moe_gemm_h<MD, HD, 2>,
                             cudaFuncAttributeMaxDynamicSharedMemorySize, GEMM_SMEM);
    }

    __half* w1h; cudaGetSymbolAddress((void**)&w1h, g_w1h);
    __half* w2h; cudaGetSymbolAddress((void**)&w2h, g_w2h);

    // fork: weight conversions on side stream, overlapping routing + phase-1
    cudaEventRecord(evFork, 0);
    cudaStreamWaitEvent(s2, evFork, 0);
    cvt_half_kernel<<<(int)(((size_t)NE*HD*MD/4) / 256), 256, 0, s2>>>(W1, w1h);
    cudaEventRecord(evW1, s2);
    cvt_half_kernel<<<(int)(((size_t)NE*MD*HD/4) / 256), 256, 0, s2>>>(W2, w2h);
    cudaEventRecord(evW2, s2);

    // main stream: routing chain
    init_kernel<<<1, 32>>>();
    gate_kernel<<<TOK / 8, 256>>>(X, Wg, bg);
    scan_kernel<<<1, 32>>>();
    scatter_kernel<<<RT / 256, 256>>>();
    gather_cvt<<<RT, 256>>>(X);

    // join W1, run phase 1 (W2 conversion still running concurrently)
    cudaStreamWaitEvent(0, evW1, 0);
    moe_gemm_h<HD, MD, 1><<<dim3(MD / 256, RT / 128, NE), 256, GEMM_SMEM>>>(b1);

    // join W2, run phase 2
    cudaStreamWaitEvent(0, evW2, 0);
    moe_gemm_h<MD, HD, 2><<<dim3(HD / 256, RT / 128, NE), 256, GEMM_SMEM>>>(b2);

    combine_kernel<<<TOK * HD / 1024, 256>>>(out);
}

// round 10
// speedup vs baseline: 1.2280x; 1.2280x over previous
#include <cuda_runtime.h>
#include <cuda_fp16.h>
#include <cstdint>
#include <cstddef>

#define TOK 16384
#define HD 1024
#define MD 2048
#define NE 16
#define RT (TOK*2)

// ---------------- scratch (device globals: allocation-free) ----------------
__device__ int    g_cnt[NE];
__device__ int    g_cur[NE];
__device__ int    g_offs[NE+1];
__device__ int    g_texp[RT];
__device__ float  g_tw[RT];
__device__ int    g_ptok[RT];
__device__ float  g_pw[RT];
__device__ int    g_pos[RT];
__device__ __half g_xah [(size_t)TOK * HD];     // fp16 X, token-indexed (34MB)
__device__ __half g_w1h [(size_t)NE * HD * MD]; // W1 fp16, original [e][k][n] layout
__device__ __half g_w2h [(size_t)NE * MD * HD]; // W2 fp16, original [e][k][n] layout
__device__ __half g_hmidh[(size_t)RT * MD];     // intermediate, fp16 (134MB)
__device__ float  g_y   [(size_t)RT * HD];      // per-(token,expert) outputs fp32

// ---------------- helpers ----------------
__device__ __forceinline__ uint32_t smem_u32(const void* p){
    uint32_t a;
    asm("{ .reg .u64 t; cvta.to.shared.u64 t, %1; cvt.u32.u64 %0, t; }" : "=r"(a) : "l"(p));
    return a;
}
__device__ __forceinline__ void cpa16(uint32_t dst, const void* src, bool valid){
    asm volatile("cp.async.cg.shared.global [%0], [%1], 16, %2;\n"
                 :: "r"(dst), "l"(src), "r"(valid ? 16 : 0) : "memory");
}
__device__ __forceinline__ void ldsm4(uint32_t* r, uint32_t addr){
    asm volatile("ldmatrix.sync.aligned.m8n8.x4.shared.b16 {%0,%1,%2,%3}, [%4];"
                 : "=r"(r[0]), "=r"(r[1]), "=r"(r[2]), "=r"(r[3]) : "r"(addr));
}
__device__ __forceinline__ void ldsm4t(uint32_t* r, uint32_t addr){
    asm volatile("ldmatrix.sync.aligned.m8n8.x4.trans.shared.b16 {%0,%1,%2,%3}, [%4];"
                 : "=r"(r[0]), "=r"(r[1]), "=r"(r[2]), "=r"(r[3]) : "r"(addr));
}
__device__ __forceinline__ void mma_f16(float* c, const uint32_t* a, const uint32_t* b){
    asm volatile("mma.sync.aligned.m16n8k16.row.col.f32.f16.f16.f32 "
        "{%0,%1,%2,%3}, {%4,%5,%6,%7}, {%8,%9}, {%0,%1,%2,%3};"
        : "+f"(c[0]), "+f"(c[1]), "+f"(c[2]), "+f"(c[3])
        : "r"(a[0]), "r"(a[1]), "r"(a[2]), "r"(a[3]), "r"(b[0]), "r"(b[1]));
}

// ---------------- routing kernels ----------------
__global__ void init_kernel(){
    int i = threadIdx.x;
    if (i < NE){ g_cnt[i] = 0; g_cur[i] = 0; }
}

// gate: one token per thread, Wg resident in SMEM (broadcast reads),
// X tiles staged in SMEM; also emits fp16 X (token-indexed) as a side product.
static constexpr int GATE_SMEM = 1024*16*4 + 128*68*4 + 64;   // 100416
__global__ __launch_bounds__(128)
void gate_kernel(const float* __restrict__ X,
                 const float* __restrict__ Wg, const float* __restrict__ bg){
    extern __shared__ float gsm[];
    float* sWg = gsm;             // [1024][16]
    float* sX  = gsm + 1024*16;   // [128][68] (stride 68: float4-safe, conflict-free)
    int*   scnt = (int*)(gsm + 1024*16 + 128*68);

    const int tid = threadIdx.x;
    const int t0  = blockIdx.x * 128;

    if (tid < NE) scnt[tid] = 0;
    // preload Wg (16384 floats, 32 float4 per thread)
    #pragma unroll
    for (int i = 0; i < 32; i++){
        int f = i * 128 + tid;
        *(float4*)&sWg[f * 4] = ((const float4*)Wg)[f];
    }

    float acc[NE];
    #pragma unroll
    for (int e = 0; e < NE; e++) acc[e] = 0.f;

    for (int hb = 0; hb < HD; hb += 64){
        __syncthreads();
        // stage X[128][64] coalesced + emit fp16
        #pragma unroll
        for (int i = 0; i < 16; i++){
            int f = i * 128 + tid;
            int row = f >> 4, c4 = (f & 15) * 4;
            float4 v = *(const float4*)(X + (size_t)(t0 + row) * HD + hb + c4);
            *(float4*)&sX[row * 68 + c4] = v;
            __half2 h0 = __floats2half2_rn(v.x, v.y);
            __half2 h1 = __floats2half2_rn(v.z, v.w);
            __half2* dst = (__half2*)(g_xah + (size_t)(t0 + row) * HD + hb + c4);
            dst[0] = h0; dst[1] = h1;
        }
        __syncthreads();
        // compute: token tid, broadcast Wg rows
        #pragma unroll 4
        for (int h4 = 0; h4 < 64; h4 += 4){
            float4 x = *(const float4*)&sX[tid * 68 + h4];
            const float xs[4] = {x.x, x.y, x.z, x.w};
            #pragma unroll
            for (int j = 0; j < 4; j++){
                const float4* w4 = (const float4*)&sWg[(hb + h4 + j) * 16];
                float xv = xs[j];
                #pragma unroll
                for (int q = 0; q < 4; q++){
                    float4 w = w4[q];
                    acc[4*q+0] += xv * w.x; acc[4*q+1] += xv * w.y;
                    acc[4*q+2] += xv * w.z; acc[4*q+3] += xv * w.w;
                }
            }
        }
    }

    // finalize: bias, top-2, renormalized softmax weights
    #pragma unroll
    for (int e = 0; e < NE; e++) acc[e] += bg[e];
    int i1 = 0;
    #pragma unroll
    for (int e = 1; e < NE; e++) if (acc[e] > acc[i1]) i1 = e;
    int i2 = (i1 == 0) ? 1 : 0;
    #pragma unroll
    for (int e = 0; e < NE; e++) if (e != i1 && acc[e] > acc[i2]) i2 = e;
    float w1 = 1.f / (1.f + expf(acc[i2] - acc[i1]));
    float w2 = 1.f - w1;
    const int t = t0 + tid;
    g_texp[2*t]   = i1; g_tw[2*t]   = w1;
    g_texp[2*t+1] = i2; g_tw[2*t+1] = w2;
    atomicAdd(&scnt[i1], 1); atomicAdd(&scnt[i2], 1);
    __syncthreads();
    if (tid < NE) atomicAdd(&g_cnt[tid], scnt[tid]);
}

__global__ void scan_kernel(){
    if (threadIdx.x == 0){
        int s = 0;
        for (int e = 0; e < NE; e++){ g_offs[e] = s; s += g_cnt[e]; }
        g_offs[NE] = s;
    }
}

__global__ __launch_bounds__(256) void scatter_kernel(){
    int i = blockIdx.x * 256 + threadIdx.x;
    int e = g_texp[i];
    int p = g_offs[e] + atomicAdd(&g_cur[e], 1);
    g_ptok[p] = i >> 1;
    g_pw[p]   = g_tw[i];
    g_pos[i]  = p;
}

// ---------------- pre-pass: fp32 -> fp16 weights ----------------
__global__ __launch_bounds__(256) void cvt_half_kernel(const float* __restrict__ src,
                                                       __half* __restrict__ dst){
    size_t i = (size_t)blockIdx.x * 256 + threadIdx.x;   // one float4 per thread
    float4 v = ((const float4*)src)[i];
    __half2* d2 = (__half2*)dst;
    d2[2*i]   = __floats2half2_rn(v.x, v.y);
    d2[2*i+1] = __floats2half2_rn(v.z, v.w);
}

// ---------------- fp16 grouped GEMM, BK=32, 4-stage cp.async pipeline -------
// PHASE 1: hmid[p,:] = f16(relu(xah[tok(p),:] @ W1[e] + b1[e]))  (KD=HD, ND=MD)
// PHASE 2: y[p,:]    = pw(p) * (hmid[p,:] @ W2[e] + b2[e])       (KD=MD, ND=HD)
static constexpr int GEMM_SMEM = 1024 + 4*(128*40*2) + 4*(32*264*2);  // 109568

template<int KD, int ND, int PHASE>
__global__ __launch_bounds__(256, 1)
void moe_gemm_h(const float* __restrict__ bias)
{
    constexpr int BM = 128, BN = 256, BK = 32, S = 4;
    constexpr int NC = KD / BK;
    constexpr int ASTRB = 80;     // bytes per A SMEM row (32 halves + 8 pad)
    constexpr int BSTRB = 528;    // bytes per B SMEM row (256 halves + 8 pad)
    constexpr int ABYTES = BM * ASTRB;   // 10240
    constexpr int BBYTES = BK * BSTRB;   // 16896
    extern __shared__ char smem[];
    float* bias_s = (float*)smem;
    const uint32_t As0 = smem_u32(smem + 1024);
    const uint32_t Bs0 = As0 + S * ABYTES;

    const int e = blockIdx.z;
    const int start = g_offs[e];
    const int rows  = g_offs[e+1] - start;
    const int m0 = blockIdx.y * BM;
    if (m0 >= rows) return;
    const int n0 = blockIdx.x * BN;
    const int tid = threadIdx.x, wid = tid >> 5, lane = tid & 31;

    const __half* Ab = (PHASE == 1) ? (const __half*)g_xah : (const __half*)g_hmidh;
    const __half* Wh = (PHASE == 1) ? (const __half*)g_w1h : (const __half*)g_w2h;

    bias_s[tid] = bias[(size_t)e * ND + n0 + tid];

    // staging assignment (phase 1: A rows via token indirection)
    const int ar = tid >> 1, ac = tid & 1;          // A: row, 32B-half
    const bool a_ok = (m0 + ar) < rows;
    size_t arow;
    if (PHASE == 1) arow = (size_t)g_ptok[start + m0 + (a_ok ? ar : 0)];
    else            arow = (size_t)(start + m0 + (a_ok ? ar : 0));
    const __half* a_srcrow = Ab + arow * KD + ac * 16;
    const uint32_t a_doff = (uint32_t)(ar * ASTRB + ac * 32);
    const int br = tid >> 3, bc = tid & 7;          // B: k-row, 64B col chunk
    const __half* b_srcrow = Wh + ((size_t)e * KD + br) * ND + n0 + bc * 32;
    const uint32_t b_doff = (uint32_t)(br * BSTRB + bc * 64);

    auto stage = [&](int c, int slot){
        uint32_t Abase = As0 + slot * ABYTES;
        uint32_t Bbase = Bs0 + slot * BBYTES;
        const __half* as = a_srcrow + c * BK;
        cpa16(Abase + a_doff,      as,     a_ok);
        cpa16(Abase + a_doff + 16, as + 8, a_ok);
        const __half* bs = b_srcrow + (size_t)c * BK * ND;
        #pragma unroll
        for (int j = 0; j < 4; j++) cpa16(Bbase + b_doff + j*16, bs + j*8, true);
    };

    // prologue: stages 0..S-2
    #pragma unroll
    for (int i = 0; i < S-1; i++){
        stage(i, i);
        asm volatile("cp.async.commit_group;" ::: "memory");
    }

    // per-lane fragment addressing
    const int wm = (wid & 1) * 64, wn = (wid >> 1) * 64;
    const int g = lane >> 3, lr = lane & 7, gq = lane >> 2, tq = lane & 3;
    const uint32_t aoff = (uint32_t)((wm + (g & 1) * 8 + lr) * ASTRB + (g >> 1) * 16);
    const uint32_t boff = (uint32_t)(((g & 1) * 8 + lr) * BSTRB + (g >> 1) * 16 + wn * 2);

    float c[4][8][4];
    #pragma unroll
    for (int a = 0; a < 4; a++)
        #pragma unroll
        for (int b = 0; b < 8; b++)
            #pragma unroll
            for (int k = 0; k < 4; k++) c[a][b][k] = 0.f;

    for (int i = 0; i < NC; i++){
        asm volatile("cp.async.wait_group %0;" :: "n"(S-2) : "memory");
        __syncthreads();
        if (i + S - 1 < NC) stage(i + S - 1, (i + S - 1) & (S - 1));
        asm volatile("cp.async.commit_group;" ::: "memory");

        const uint32_t Abase = As0 + (i & (S-1)) * ABYTES + aoff;
        const uint32_t Bbase = Bs0 + (i & (S-1)) * BBYTES + boff;
        #pragma unroll
        for (int ks = 0; ks < 2; ks++){
            uint32_t af[4][4], bf[4][4];
            #pragma unroll
            for (int mt = 0; mt < 4; mt++)
                ldsm4(af[mt], Abase + mt * (16 * ASTRB) + ks * 32);
            #pragma unroll
            for (int nt = 0; nt < 4; nt++)
                ldsm4t(bf[nt], Bbase + ks * (16 * BSTRB) + nt * 32);
            #pragma unroll
            for (int mt = 0; mt < 4; mt++)
                #pragma unroll
                for (int nt = 0; nt < 4; nt++){
                    mma_f16(c[mt][2*nt],   af[mt], bf[nt]);
                    mma_f16(c[mt][2*nt+1], af[mt], bf[nt] + 2);
                }
        }
    }

    // ---------------- epilogue ----------------
    #pragma unroll
    for (int mt = 0; mt < 4; mt++){
        const int r0l = wm + mt * 16 + gq;
        const int r1l = r0l + 8;
        const bool v0 = (m0 + r0l) < rows;
        const bool v1 = (m0 + r1l) < rows;
        const size_t gr0 = (size_t)(start + m0 + (v0 ? r0l : 0));
        const size_t gr1 = (size_t)(start + m0 + (v1 ? r1l : 0));
        float pw0 = 0.f, pw1 = 0.f;
        if (PHASE == 2){
            pw0 = v0 ? g_pw[gr0] : 0.f;
            pw1 = v1 ? g_pw[gr1] : 0.f;
        }
        #pragma unroll
        for (int j = 0; j < 8; j++){
            const int nw = (j >> 1) * 16 + (j & 1) * 8;
            const int n = wn + nw + 2 * tq;
            const float bb0 = bias_s[n], bb1 = bias_s[n + 1];
            float v00 = c[mt][j][0] + bb0, v01 = c[mt][j][1] + bb1;
            float v10 = c[mt][j][2] + bb0, v11 = c[mt][j][3] + bb1;
            if (PHASE == 1){
                if (v0)
                    *(__half2*)(g_hmidh + gr0 * ND + n0 + n) =
                        __floats2half2_rn(fmaxf(v00, 0.f), fmaxf(v01, 0.f));
                if (v1)
                    *(__half2*)(g_hmidh + gr1 * ND + n0 + n) =
                        __floats2half2_rn(fmaxf(v10, 0.f), fmaxf(v11, 0.f));
            } else {
                if (v0)
                    *(float2*)(g_y + gr0 * ND + n0 + n) = make_float2(v00 * pw0, v01 * pw0);
                if (v1)
                    *(float2*)(g_y + gr1 * ND + n0 + n) = make_float2(v10 * pw1, v11 * pw1);
            }
        }
    }
}

// ---------------- combine: out[t] = Y[pos(t,0)] + Y[pos(t,1)] ----------------
__global__ __launch_bounds__(256) void combine_kernel(float* __restrict__ out){
    size_t idx = (size_t)blockIdx.x * 256 + threadIdx.x;
    int t = (int)(idx >> 8);
    int j = (int)(idx & 255);
    int p0 = g_pos[2 * t], p1 = g_pos[2 * t + 1];
    const float4* Y4 = (const float4*)g_y;
    float4 a = Y4[(size_t)p0 * (HD / 4) + j];
    float4 b = Y4[(size_t)p1 * (HD / 4) + j];
    ((float4*)out)[idx] = make_float4(a.x + b.x, a.y + b.y, a.z + b.z, a.w + b.w);
}

// ---------------- launch ----------------
extern "C" void kernel_launch(void* const* d_in, const int* in_sizes, int n_in,
                              void* d_out, int out_size) {
    const float* X  = (const float*)d_in[0];
    const float* Wg = (const float*)d_in[1];
    const float* bg = (const float*)d_in[2];
    const float* W1 = (const float*)d_in[3];
    const float* b1 = (const float*)d_in[4];
    const float* W2 = (const float*)d_in[5];
    const float* b2 = (const float*)d_in[6];
    float* out = (float*)d_out;

    cudaFuncSetAttribute(gate_kernel,
                         cudaFuncAttributeMaxDynamicSharedMemorySize, GATE_SMEM);
    cudaFuncSetAttribute(moe_gemm_h<HD, MD, 1>,
                         cudaFuncAttributeMaxDynamicSharedMemorySize, GEMM_SMEM);
    cudaFuncSetAttribute(moe_gemm_h<MD, HD, 2>,
                         cudaFuncAttributeMaxDynamicSharedMemorySize, GEMM_SMEM);

    __half* w1h; cudaGetSymbolAddress((void**)&w1h, g_w1h);
    __half* w2h; cudaGetSymbolAddress((void**)&w2h, g_w2h);

    init_kernel<<<1, 32>>>();
    gate_kernel<<<TOK / 128, 128, GATE_SMEM>>>(X, Wg, bg);
    scan_kernel<<<1, 32>>>();
    scatter_kernel<<<RT / 256, 256>>>();
    cvt_half_kernel<<<(int)(((size_t)NE*HD*MD/4) / 256), 256>>>(W1, w1h);
    cvt_half_kernel<<<(int)(((size_t)NE*MD*HD/4) / 256), 256>>>(W2, w2h);
    moe_gemm_h<HD, MD, 1><<<dim3(MD / 256, RT / 128, NE), 256, GEMM_SMEM>>>(b1);
    moe_gemm_h<MD, HD, 2><<<dim3(HD / 256, RT / 128, NE), 256, GEMM_SMEM>>>(b2);
    combine_kernel<<<TOK * HD / 1024, 256>>>(out);
}

// round 12
// speedup vs baseline: 1.2482x; 1.0164x over previous
#include <cuda_runtime.h>
#include <cuda_fp16.h>
#include <cstdint>
#include <cstddef>

#define TOK 16384
#define HD 1024
#define MD 2048
#define NE 16
#define RT (TOK*2)

// ---------------- scratch (device globals: allocation-free) ----------------
__device__ int    g_cnt[NE];
__device__ int    g_cur[NE];
__device__ int    g_offs[NE+1];
__device__ int    g_texp[RT];
__device__ float  g_tw[RT];
__device__ int    g_ptok[RT];
__device__ float  g_pw[RT];
__device__ int    g_pos[RT];
__device__ __half g_xah [(size_t)TOK * HD];     // fp16 X, token-indexed (34MB)
__device__ __half g_w1h [(size_t)NE * HD * MD]; // W1 fp16, original [e][k][n] layout
__device__ __half g_w2h [(size_t)NE * MD * HD]; // W2 fp16, original [e][k][n] layout
__device__ __half g_hmidh[(size_t)RT * MD];     // intermediate, fp16 (134MB)
__device__ __half g_yh  [(size_t)RT * HD];      // per-(token,expert) outputs fp16 (67MB)

// ---------------- helpers ----------------
__device__ __forceinline__ uint32_t smem_u32(const void* p){
    uint32_t a;
    asm("{ .reg .u64 t; cvta.to.shared.u64 t, %1; cvt.u32.u64 %0, t; }" : "=r"(a) : "l"(p));
    return a;
}
__device__ __forceinline__ void cpa16(uint32_t dst, const void* src, bool valid){
    asm volatile("cp.async.cg.shared.global [%0], [%1], 16, %2;\n"
                 :: "r"(dst), "l"(src), "r"(valid ? 16 : 0) : "memory");
}
__device__ __forceinline__ void ldsm4(uint32_t* r, uint32_t addr){
    asm volatile("ldmatrix.sync.aligned.m8n8.x4.shared.b16 {%0,%1,%2,%3}, [%4];"
                 : "=r"(r[0]), "=r"(r[1]), "=r"(r[2]), "=r"(r[3]) : "r"(addr));
}
__device__ __forceinline__ void ldsm4t(uint32_t* r, uint32_t addr){
    asm volatile("ldmatrix.sync.aligned.m8n8.x4.trans.shared.b16 {%0,%1,%2,%3}, [%4];"
                 : "=r"(r[0]), "=r"(r[1]), "=r"(r[2]), "=r"(r[3]) : "r"(addr));
}
__device__ __forceinline__ void mma_f16(float* c, const uint32_t* a, const uint32_t* b){
    asm volatile("mma.sync.aligned.m16n8k16.row.col.f32.f16.f16.f32 "
        "{%0,%1,%2,%3}, {%4,%5,%6,%7}, {%8,%9}, {%0,%1,%2,%3};"
        : "+f"(c[0]), "+f"(c[1]), "+f"(c[2]), "+f"(c[3])
        : "r"(a[0]), "r"(a[1]), "r"(a[2]), "r"(a[3]), "r"(b[0]), "r"(b[1]));
}

// ---------------- routing kernels ----------------
__global__ void init_kernel(){
    int i = threadIdx.x;
    if (i < NE){ g_cnt[i] = 0; g_cur[i] = 0; }
}

// gate: one token per thread, Wg resident in SMEM (broadcast reads),
// X tiles staged in SMEM; also emits fp16 X (token-indexed) as a side product.
static constexpr int GATE_SMEM = 1024*16*4 + 128*68*4 + 64;   // 100416
__global__ __launch_bounds__(128)
void gate_kernel(const float* __restrict__ X,
                 const float* __restrict__ Wg, const float* __restrict__ bg){
    extern __shared__ float gsm[];
    float* sWg = gsm;             // [1024][16]
    float* sX  = gsm + 1024*16;   // [128][68] (stride 68: float4-safe, conflict-free)
    int*   scnt = (int*)(gsm + 1024*16 + 128*68);

    const int tid = threadIdx.x;
    const int t0  = blockIdx.x * 128;

    if (tid < NE) scnt[tid] = 0;
    // preload Wg (16384 floats, 32 float4 per thread)
    #pragma unroll
    for (int i = 0; i < 32; i++){
        int f = i * 128 + tid;
        *(float4*)&sWg[f * 4] = ((const float4*)Wg)[f];
    }

    float acc[NE];
    #pragma unroll
    for (int e = 0; e < NE; e++) acc[e] = 0.f;

    for (int hb = 0; hb < HD; hb += 64){
        __syncthreads();
        // stage X[128][64] coalesced + emit fp16
        #pragma unroll
        for (int i = 0; i < 16; i++){
            int f = i * 128 + tid;
            int row = f >> 4, c4 = (f & 15) * 4;
            float4 v = *(const float4*)(X + (size_t)(t0 + row) * HD + hb + c4);
            *(float4*)&sX[row * 68 + c4] = v;
            __half2 h0 = __floats2half2_rn(v.x, v.y);
            __half2 h1 = __floats2half2_rn(v.z, v.w);
            __half2* dst = (__half2*)(g_xah + (size_t)(t0 + row) * HD + hb + c4);
            dst[0] = h0; dst[1] = h1;
        }
        __syncthreads();
        // compute: token tid, broadcast Wg rows
        #pragma unroll 4
        for (int h4 = 0; h4 < 64; h4 += 4){
            float4 x = *(const float4*)&sX[tid * 68 + h4];
            const float xs[4] = {x.x, x.y, x.z, x.w};
            #pragma unroll
            for (int j = 0; j < 4; j++){
                const float4* w4 = (const float4*)&sWg[(hb + h4 + j) * 16];
                float xv = xs[j];
                #pragma unroll
                for (int q = 0; q < 4; q++){
                    float4 w = w4[q];
                    acc[4*q+0] += xv * w.x; acc[4*q+1] += xv * w.y;
                    acc[4*q+2] += xv * w.z; acc[4*q+3] += xv * w.w;
                }
            }
        }
    }

    // finalize: bias, top-2, renormalized softmax weights
    #pragma unroll
    for (int e = 0; e < NE; e++) acc[e] += bg[e];
    int i1 = 0;
    #pragma unroll
    for (int e = 1; e < NE; e++) if (acc[e] > acc[i1]) i1 = e;
    int i2 = (i1 == 0) ? 1 : 0;
    #pragma unroll
    for (int e = 0; e < NE; e++) if (e != i1 && acc[e] > acc[i2]) i2 = e;
    float w1 = 1.f / (1.f + expf(acc[i2] - acc[i1]));
    float w2 = 1.f - w1;
    const int t = t0 + tid;
    g_texp[2*t]   = i1; g_tw[2*t]   = w1;
    g_texp[2*t+1] = i2; g_tw[2*t+1] = w2;
    atomicAdd(&scnt[i1], 1); atomicAdd(&scnt[i2], 1);
    __syncthreads();
    if (tid < NE) atomicAdd(&g_cnt[tid], scnt[tid]);
}

__global__ void scan_kernel(){
    if (threadIdx.x == 0){
        int s = 0;
        for (int e = 0; e < NE; e++){ g_offs[e] = s; s += g_cnt[e]; }
        g_offs[NE] = s;
    }
}

__global__ __launch_bounds__(256) void scatter_kernel(){
    int i = blockIdx.x * 256 + threadIdx.x;
    int e = g_texp[i];
    int p = g_offs[e] + atomicAdd(&g_cur[e], 1);
    g_ptok[p] = i >> 1;
    g_pw[p]   = g_tw[i];
    g_pos[i]  = p;
}

// ---------------- pre-pass: fp32 -> fp16 weights ----------------
__global__ __launch_bounds__(256) void cvt_half_kernel(const float* __restrict__ src,
                                                       __half* __restrict__ dst){
    size_t i = (size_t)blockIdx.x * 256 + threadIdx.x;   // one float4 per thread
    float4 v = ((const float4*)src)[i];
    __half2* d2 = (__half2*)dst;
    d2[2*i]   = __floats2half2_rn(v.x, v.y);
    d2[2*i+1] = __floats2half2_rn(v.z, v.w);
}

// ---------------- fp16 grouped GEMM, BK=32, 4-stage cp.async pipeline -------
// PHASE 1: hmid[p,:] = f16(relu(xah[tok(p),:] @ W1[e] + b1[e]))  (KD=HD, ND=MD)
// PHASE 2: yh[p,:]   = f16(pw(p) * (hmid[p,:] @ W2[e] + b2[e]))  (KD=MD, ND=HD)
static constexpr int GEMM_SMEM = 1024 + 4*(128*40*2) + 4*(32*264*2);  // 109568

template<int KD, int ND, int PHASE>
__global__ __launch_bounds__(256, 1)
void moe_gemm_h(const float* __restrict__ bias)
{
    constexpr int BM = 128, BN = 256, BK = 32, S = 4;
    constexpr int NC = KD / BK;
    constexpr int ASTRB = 80;     // bytes per A SMEM row (32 halves + 8 pad)
    constexpr int BSTRB = 528;    // bytes per B SMEM row (256 halves + 8 pad)
    constexpr int ABYTES = BM * ASTRB;   // 10240
    constexpr int BBYTES = BK * BSTRB;   // 16896
    extern __shared__ char smem[];
    float* bias_s = (float*)smem;
    const uint32_t As0 = smem_u32(smem + 1024);
    const uint32_t Bs0 = As0 + S * ABYTES;

    const int e = blockIdx.z;
    const int start = g_offs[e];
    const int rows  = g_offs[e+1] - start;
    const int m0 = blockIdx.y * BM;
    if (m0 >= rows) return;
    const int n0 = blockIdx.x * BN;
    const int tid = threadIdx.x, wid = tid >> 5, lane = tid & 31;

    const __half* Ab = (PHASE == 1) ? (const __half*)g_xah : (const __half*)g_hmidh;
    const __half* Wh = (PHASE == 1) ? (const __half*)g_w1h : (const __half*)g_w2h;

    bias_s[tid] = bias[(size_t)e * ND + n0 + tid];

    // staging assignment (phase 1: A rows via token indirection)
    const int ar = tid >> 1, ac = tid & 1;          // A: row, 32B-half
    const bool a_ok = (m0 + ar) < rows;
    size_t arow;
    if (PHASE == 1) arow = (size_t)g_ptok[start + m0 + (a_ok ? ar : 0)];
    else            arow = (size_t)(start + m0 + (a_ok ? ar : 0));
    const __half* a_srcrow = Ab + arow * KD + ac * 16;
    const uint32_t a_doff = (uint32_t)(ar * ASTRB + ac * 32);
    const int br = tid >> 3, bc = tid & 7;          // B: k-row, 64B col chunk
    const __half* b_srcrow = Wh + ((size_t)e * KD + br) * ND + n0 + bc * 32;
    const uint32_t b_doff = (uint32_t)(br * BSTRB + bc * 64);

    auto stage = [&](int c, int slot){
        uint32_t Abase = As0 + slot * ABYTES;
        uint32_t Bbase = Bs0 + slot * BBYTES;
        const __half* as = a_srcrow + c * BK;
        cpa16(Abase + a_doff,      as,     a_ok);
        cpa16(Abase + a_doff + 16, as + 8, a_ok);
        const __half* bs = b_srcrow + (size_t)c * BK * ND;
        #pragma unroll
        for (int j = 0; j < 4; j++) cpa16(Bbase + b_doff + j*16, bs + j*8, true);
    };

    // prologue: stages 0..S-2
    #pragma unroll
    for (int i = 0; i < S-1; i++){
        stage(i, i);
        asm volatile("cp.async.commit_group;" ::: "memory");
    }

    // per-lane fragment addressing
    const int wm = (wid & 1) * 64, wn = (wid >> 1) * 64;
    const int g = lane >> 3, lr = lane & 7, gq = lane >> 2, tq = lane & 3;
    const uint32_t aoff = (uint32_t)((wm + (g & 1) * 8 + lr) * ASTRB + (g >> 1) * 16);
    const uint32_t boff = (uint32_t)(((g & 1) * 8 + lr) * BSTRB + (g >> 1) * 16 + wn * 2);

    float c[4][8][4];
    #pragma unroll
    for (int a = 0; a < 4; a++)
        #pragma unroll
        for (int b = 0; b < 8; b++)
            #pragma unroll
            for (int k = 0; k < 4; k++) c[a][b][k] = 0.f;

    for (int i = 0; i < NC; i++){
        asm volatile("cp.async.wait_group %0;" :: "n"(S-2) : "memory");
        __syncthreads();
        if (i + S - 1 < NC) stage(i + S - 1, (i + S - 1) & (S - 1));
        asm volatile("cp.async.commit_group;" ::: "memory");

        const uint32_t Abase = As0 + (i & (S-1)) * ABYTES + aoff;
        const uint32_t Bbase = Bs0 + (i & (S-1)) * BBYTES + boff;
        #pragma unroll
        for (int ks = 0; ks < 2; ks++){
            uint32_t af[4][4], bf[4][4];
            #pragma unroll
            for (int mt = 0; mt < 4; mt++)
                ldsm4(af[mt], Abase + mt * (16 * ASTRB) + ks * 32);
            #pragma unroll
            for (int nt = 0; nt < 4; nt++)
                ldsm4t(bf[nt], Bbase + ks * (16 * BSTRB) + nt * 32);
            #pragma unroll
            for (int mt = 0; mt < 4; mt++)
                #pragma unroll
                for (int nt = 0; nt < 4; nt++){
                    mma_f16(c[mt][2*nt],   af[mt], bf[nt]);
                    mma_f16(c[mt][2*nt+1], af[mt], bf[nt] + 2);
                }
        }
    }

    // ---------------- epilogue ----------------
    #pragma unroll
    for (int mt = 0; mt < 4; mt++){
        const int r0l = wm + mt * 16 + gq;
        const int r1l = r0l + 8;
        const bool v0 = (m0 + r0l) < rows;
        const bool v1 = (m0 + r1l) < rows;
        const size_t gr0 = (size_t)(start + m0 + (v0 ? r0l : 0));
        const size_t gr1 = (size_t)(start + m0 + (v1 ? r1l : 0));
        float pw0 = 0.f, pw1 = 0.f;
        if (PHASE == 2){
            pw0 = v0 ? g_pw[gr0] : 0.f;
            pw1 = v1 ? g_pw[gr1] : 0.f;
        }
        #pragma unroll
        for (int j = 0; j < 8; j++){
            const int nw = (j >> 1) * 16 + (j & 1) * 8;
            const int n = wn + nw + 2 * tq;
            const float bb0 = bias_s[n], bb1 = bias_s[n + 1];
            float v00 = c[mt][j][0] + bb0, v01 = c[mt][j][1] + bb1;
            float v10 = c[mt][j][2] + bb0, v11 = c[mt][j][3] + bb1;
            if (PHASE == 1){
                if (v0)
                    *(__half2*)(g_hmidh + gr0 * ND + n0 + n) =
                        __floats2half2_rn(fmaxf(v00, 0.f), fmaxf(v01, 0.f));
                if (v1)
                    *(__half2*)(g_hmidh + gr1 * ND + n0 + n) =
                        __floats2half2_rn(fmaxf(v10, 0.f), fmaxf(v11, 0.f));
            } else {
                if (v0)
                    *(__half2*)(g_yh + gr0 * ND + n0 + n) =
                        __floats2half2_rn(v00 * pw0, v01 * pw0);
                if (v1)
                    *(__half2*)(g_yh + gr1 * ND + n0 + n) =
                        __floats2half2_rn(v10 * pw1, v11 * pw1);
            }
        }
    }
}

// ---------------- combine: out[t] = Y[pos(t,0)] + Y[pos(t,1)] ----------------
__global__ __launch_bounds__(256) void combine_kernel(float* __restrict__ out){
    size_t idx = (size_t)blockIdx.x * 256 + threadIdx.x;   // one float4 (4 outs)
    int t = (int)(idx >> 8);
    int j = (int)(idx & 255);
    int p0 = g_pos[2 * t], p1 = g_pos[2 * t + 1];
    const __half2* a2 = (const __half2*)(g_yh + (size_t)p0 * HD) + 2 * j;
    const __half2* b2 = (const __half2*)(g_yh + (size_t)p1 * HD) + 2 * j;
    float2 a0 = __half22float2(a2[0]), a1 = __half22float2(a2[1]);
    float2 c0 = __half22float2(b2[0]), c1 = __half22float2(b2[1]);
    ((float4*)out)[idx] = make_float4(a0.x + c0.x, a0.y + c0.y,
                                      a1.x + c1.x, a1.y + c1.y);
}

// ---------------- launch ----------------
extern "C" void kernel_launch(void* const* d_in, const int* in_sizes, int n_in,
                              void* d_out, int out_size) {
    const float* X  = (const float*)d_in[0];
    const float* Wg = (const float*)d_in[1];
    const float* bg = (const float*)d_in[2];
    const float* W1 = (const float*)d_in[3];
    const float* b1 = (const float*)d_in[4];
    const float* W2 = (const float*)d_in[5];
    const float* b2 = (const float*)d_in[6];
    float* out = (float*)d_out;

    // one-time host-side resources (created on the uncaptured correctness call;
    // capture sees only the fork/join edges)
    static cudaStream_t s2 = nullptr;
    static cudaEvent_t evFork = nullptr, evW1 = nullptr, evW2 = nullptr;
    if (!s2){
        cudaStreamCreateWithFlags(&s2, cudaStreamNonBlocking);
        cudaEventCreateWithFlags(&evFork, cudaEventDisableTiming);
        cudaEventCreateWithFlags(&evW1,  cudaEventDisableTiming);
        cudaEventCreateWithFlags(&evW2,  cudaEventDisableTiming);
        cudaFuncSetAttribute(gate_kernel,
                             cudaFuncAttributeMaxDynamicSharedMemorySize, GATE_SMEM);
        cudaFuncSetAttribute(moe_gemm_h<HD, MD, 1>,
                             cudaFuncAttributeMaxDynamicSharedMemorySize, GEMM_SMEM);
        cudaFuncSetAttribute(moe_gemm_h<MD, HD, 2>,
                             cudaFuncAttributeMaxDynamicSharedMemorySize, GEMM_SMEM);
    }

    __half* w1h; cudaGetSymbolAddress((void**)&w1h, g_w1h);
    __half* w2h; cudaGetSymbolAddress((void**)&w2h, g_w2h);

    // fork: weight conversions on side stream, overlapping the routing chain
    cudaEventRecord(evFork, 0);
    cudaStreamWaitEvent(s2, evFork, 0);
    cvt_half_kernel<<<(int)(((size_t)NE*HD*MD/4) / 256), 256, 0, s2>>>(W1, w1h);
    cudaEventRecord(evW1, s2);
    cvt_half_kernel<<<(int)(((size_t)NE*MD*HD/4) / 256), 256, 0, s2>>>(W2, w2h);
    cudaEventRecord(evW2, s2);

    // main stream: routing chain
    init_kernel<<<1, 32>>>();
    gate_kernel<<<TOK / 128, 128, GATE_SMEM>>>(X, Wg, bg);
    scan_kernel<<<1, 32>>>();
    scatter_kernel<<<RT / 256, 256>>>();

    // join W1, run phase 1 (W2 conversion may still be in flight)
    cudaStreamWaitEvent(0, evW1, 0);
    moe_gemm_h<HD, MD, 1><<<dim3(MD / 256, RT / 128, NE), 256, GEMM_SMEM>>>(b1);

    // join W2, run phase 2
    cudaStreamWaitEvent(0, evW2, 0);
    moe_gemm_h<MD, HD, 2><<<dim3(HD / 256, RT / 128, NE), 256, GEMM_SMEM>>>(b2);

    combine_kernel<<<TOK * HD / 1024, 256>>>(out);
}

// round 13
// speedup vs baseline: 1.2736x; 1.0204x over previous
#include <cuda_runtime.h>
#include <cuda_fp16.h>
#include <cstdint>
#include <cstddef>

#define TOK 16384
#define HD 1024
#define MD 2048
#define NE 16
#define RT (TOK*2)

// ---------------- scratch (device globals: allocation-free) ----------------
__device__ int    g_cnt[NE];
__device__ int    g_cur[NE];
__device__ int    g_offs[NE+1];
__device__ int    g_texp[RT];
__device__ float  g_tw[RT];
__device__ int    g_ptok[RT];
__device__ float  g_pw[RT];
__device__ int    g_pos[RT];
__device__ __half g_xah [(size_t)TOK * HD];     // fp16 X, token-indexed (34MB)
__device__ __half g_w1h [(size_t)NE * HD * MD]; // W1 fp16, original [e][k][n] layout
__device__ __half g_w2h [(size_t)NE * MD * HD]; // W2 fp16, original [e][k][n] layout
__device__ __half g_hmidh[(size_t)RT * MD];     // intermediate, fp16 (134MB)
__device__ __half g_yh  [(size_t)RT * HD];      // per-(token,expert) outputs fp16 (67MB)

// ---------------- helpers ----------------
__device__ __forceinline__ uint32_t smem_u32(const void* p){
    uint32_t a;
    asm("{ .reg .u64 t; cvta.to.shared.u64 t, %1; cvt.u32.u64 %0, t; }" : "=r"(a) : "l"(p));
    return a;
}
__device__ __forceinline__ void cpa16(uint32_t dst, const void* src, bool valid){
    asm volatile("cp.async.cg.shared.global [%0], [%1], 16, %2;\n"
                 :: "r"(dst), "l"(src), "r"(valid ? 16 : 0) : "memory");
}
__device__ __forceinline__ void ldsm4(uint32_t* r, uint32_t addr){
    asm volatile("ldmatrix.sync.aligned.m8n8.x4.shared.b16 {%0,%1,%2,%3}, [%4];"
                 : "=r"(r[0]), "=r"(r[1]), "=r"(r[2]), "=r"(r[3]) : "r"(addr));
}
__device__ __forceinline__ void ldsm4t(uint32_t* r, uint32_t addr){
    asm volatile("ldmatrix.sync.aligned.m8n8.x4.trans.shared.b16 {%0,%1,%2,%3}, [%4];"
                 : "=r"(r[0]), "=r"(r[1]), "=r"(r[2]), "=r"(r[3]) : "r"(addr));
}
__device__ __forceinline__ void mma_f16(float* c, const uint32_t* a, const uint32_t* b){
    asm volatile("mma.sync.aligned.m16n8k16.row.col.f32.f16.f16.f32 "
        "{%0,%1,%2,%3}, {%4,%5,%6,%7}, {%8,%9}, {%0,%1,%2,%3};"
        : "+f"(c[0]), "+f"(c[1]), "+f"(c[2]), "+f"(c[3])
        : "r"(a[0]), "r"(a[1]), "r"(a[2]), "r"(a[3]), "r"(b[0]), "r"(b[1]));
}

// ---------------- routing kernels ----------------
__global__ void init_kernel(){
    int i = threadIdx.x;
    if (i < NE){ g_cnt[i] = 0; g_cur[i] = 0; }
}

// gate: 128 tokens/block, 256 threads, 2 threads per token (each half of H),
// Wg resident in SMEM (broadcast reads), X tiles staged in SMEM;
// emits fp16 X (token-indexed) as a side product.
static constexpr int GATE_SMEM = 1024*16*4 + 128*68*4 + 128*16*4 + 64; // 108608
__global__ __launch_bounds__(256)
void gate_kernel(const float* __restrict__ X,
                 const float* __restrict__ Wg, const float* __restrict__ bg){
    extern __shared__ float gsm[];
    float* sWg  = gsm;                      // [1024][16]
    float* sX   = gsm + 1024*16;            // [128][68] (stride 68: conflict-free)
    float* sRed = gsm + 1024*16 + 128*68;   // [128][16] partial accs (upper half)
    int*   scnt = (int*)(sRed + 128*16);

    const int tid   = threadIdx.x;
    const int token = tid & 127;
    const int half  = tid >> 7;             // 0: h[0..32), 1: h[32..64) per chunk
    const int t0    = blockIdx.x * 128;

    if (tid < NE) scnt[tid] = 0;
    // preload Wg (16384 floats = 4096 float4, 16 per thread)
    #pragma unroll
    for (int i = 0; i < 16; i++){
        int f = i * 256 + tid;
        *(float4*)&sWg[f * 4] = ((const float4*)Wg)[f];
    }

    float acc[NE];
    #pragma unroll
    for (int e = 0; e < NE; e++) acc[e] = 0.f;

    for (int hb = 0; hb < HD; hb += 64){
        __syncthreads();
        // stage X[128][64] coalesced (2048 float4, 8 per thread) + emit fp16
        #pragma unroll
        for (int i = 0; i < 8; i++){
            int f = i * 256 + tid;
            int row = f >> 4, c4 = (f & 15) * 4;
            float4 v = *(const float4*)(X + (size_t)(t0 + row) * HD + hb + c4);
            *(float4*)&sX[row * 68 + c4] = v;
            __half2 h0 = __floats2half2_rn(v.x, v.y);
            __half2 h1 = __floats2half2_rn(v.z, v.w);
            __half2* dst = (__half2*)(g_xah + (size_t)(t0 + row) * HD + hb + c4);
            dst[0] = h0; dst[1] = h1;
        }
        __syncthreads();
        // compute: this thread's 32-wide slice of the 64-chunk
        const int hoff = half * 32;
        #pragma unroll 4
        for (int h4 = 0; h4 < 32; h4 += 4){
            float4 x = *(const float4*)&sX[token * 68 + hoff + h4];
            const float xs[4] = {x.x, x.y, x.z, x.w};
            #pragma unroll
            for (int j = 0; j < 4; j++){
                const float4* w4 = (const float4*)&sWg[(hb + hoff + h4 + j) * 16];
                float xv = xs[j];
                #pragma unroll
                for (int q = 0; q < 4; q++){
                    float4 w = w4[q];
                    acc[4*q+0] += xv * w.x; acc[4*q+1] += xv * w.y;
                    acc[4*q+2] += xv * w.z; acc[4*q+3] += xv * w.w;
                }
            }
        }
    }

    // pair reduction: upper half deposits, lower half combines + finalizes
    __syncthreads();
    if (half == 1){
        #pragma unroll
        for (int e = 0; e < NE; e++) sRed[token * 16 + e] = acc[e];
    }
    __syncthreads();
    if (half == 0){
        #pragma unroll
        for (int e = 0; e < NE; e++) acc[e] += sRed[token * 16 + e] + bg[e];
        int i1 = 0;
        #pragma unroll
        for (int e = 1; e < NE; e++) if (acc[e] > acc[i1]) i1 = e;
        int i2 = (i1 == 0) ? 1 : 0;
        #pragma unroll
        for (int e = 0; e < NE; e++) if (e != i1 && acc[e] > acc[i2]) i2 = e;
        float w1 = 1.f / (1.f + expf(acc[i2] - acc[i1]));
        float w2 = 1.f - w1;
        const int t = t0 + token;
        g_texp[2*t]   = i1; g_tw[2*t]   = w1;
        g_texp[2*t+1] = i2; g_tw[2*t+1] = w2;
        atomicAdd(&scnt[i1], 1); atomicAdd(&scnt[i2], 1);
    }
    __syncthreads();
    if (tid < NE) atomicAdd(&g_cnt[tid], scnt[tid]);
}

__global__ void scan_kernel(){
    if (threadIdx.x == 0){
        int s = 0;
        for (int e = 0; e < NE; e++){ g_offs[e] = s; s += g_cnt[e]; }
        g_offs[NE] = s;
    }
}

__global__ __launch_bounds__(256) void scatter_kernel(){
    int i = blockIdx.x * 256 + threadIdx.x;
    int e = g_texp[i];
    int p = g_offs[e] + atomicAdd(&g_cur[e], 1);
    g_ptok[p] = i >> 1;
    g_pw[p]   = g_tw[i];
    g_pos[i]  = p;
}

// ---------------- pre-pass: fp32 -> fp16 weights ----------------
__global__ __launch_bounds__(256) void cvt_half_kernel(const float* __restrict__ src,
                                                       __half* __restrict__ dst){
    size_t i = (size_t)blockIdx.x * 256 + threadIdx.x;   // one float4 per thread
    float4 v = ((const float4*)src)[i];
    __half2* d2 = (__half2*)dst;
    d2[2*i]   = __floats2half2_rn(v.x, v.y);
    d2[2*i+1] = __floats2half2_rn(v.z, v.w);
}

// ---------------- fp16 grouped GEMM, BK=32, 4-stage cp.async pipeline -------
// PHASE 1: hmid[p,:] = f16(relu(xah[tok(p),:] @ W1[e] + b1[e]))  (KD=HD, ND=MD)
// PHASE 2: yh[p,:]   = f16(pw(p) * (hmid[p,:] @ W2[e] + b2[e]))  (KD=MD, ND=HD)
static constexpr int GEMM_SMEM = 1024 + 4*(128*40*2) + 4*(32*264*2);  // 109568

template<int KD, int ND, int PHASE>
__global__ __launch_bounds__(256, 1)
void moe_gemm_h(const float* __restrict__ bias)
{
    constexpr int BM = 128, BN = 256, BK = 32, S = 4;
    constexpr int NC = KD / BK;
    constexpr int ASTRB = 80;     // bytes per A SMEM row (32 halves + 8 pad)
    constexpr int BSTRB = 528;    // bytes per B SMEM row (256 halves + 8 pad)
    constexpr int ABYTES = BM * ASTRB;   // 10240
    constexpr int BBYTES = BK * BSTRB;   // 16896
    extern __shared__ char smem[];
    float* bias_s = (float*)smem;
    const uint32_t As0 = smem_u32(smem + 1024);
    const uint32_t Bs0 = As0 + S * ABYTES;

    const int e = blockIdx.z;
    const int start = g_offs[e];
    const int rows  = g_offs[e+1] - start;
    const int m0 = blockIdx.y * BM;
    if (m0 >= rows) return;
    const int n0 = blockIdx.x * BN;
    const int tid = threadIdx.x, wid = tid >> 5, lane = tid & 31;

    const __half* Ab = (PHASE == 1) ? (const __half*)g_xah : (const __half*)g_hmidh;
    const __half* Wh = (PHASE == 1) ? (const __half*)g_w1h : (const __half*)g_w2h;

    bias_s[tid] = bias[(size_t)e * ND + n0 + tid];

    // staging assignment (phase 1: A rows via token indirection)
    const int ar = tid >> 1, ac = tid & 1;          // A: row, 32B-half
    const bool a_ok = (m0 + ar) < rows;
    size_t arow;
    if (PHASE == 1) arow = (size_t)g_ptok[start + m0 + (a_ok ? ar : 0)];
    else            arow = (size_t)(start + m0 + (a_ok ? ar : 0));
    const __half* a_srcrow = Ab + arow * KD + ac * 16;
    const uint32_t a_doff = (uint32_t)(ar * ASTRB + ac * 32);
    const int br = tid >> 3, bc = tid & 7;          // B: k-row, 64B col chunk
    const __half* b_srcrow = Wh + ((size_t)e * KD + br) * ND + n0 + bc * 32;
    const uint32_t b_doff = (uint32_t)(br * BSTRB + bc * 64);

    auto stage = [&](int c, int slot){
        uint32_t Abase = As0 + slot * ABYTES;
        uint32_t Bbase = Bs0 + slot * BBYTES;
        const __half* as = a_srcrow + c * BK;
        cpa16(Abase + a_doff,      as,     a_ok);
        cpa16(Abase + a_doff + 16, as + 8, a_ok);
        const __half* bs = b_srcrow + (size_t)c * BK * ND;
        #pragma unroll
        for (int j = 0; j < 4; j++) cpa16(Bbase + b_doff + j*16, bs + j*8, true);
    };

    // prologue: stages 0..S-2
    #pragma unroll
    for (int i = 0; i < S-1; i++){
        stage(i, i);
        asm volatile("cp.async.commit_group;" ::: "memory");
    }

    // per-lane fragment addressing
    const int wm = (wid & 1) * 64, wn = (wid >> 1) * 64;
    const int g = lane >> 3, lr = lane & 7, gq = lane >> 2, tq = lane & 3;
    const uint32_t aoff = (uint32_t)((wm + (g & 1) * 8 + lr) * ASTRB + (g >> 1) * 16);
    const uint32_t boff = (uint32_t)(((g & 1) * 8 + lr) * BSTRB + (g >> 1) * 16 + wn * 2);

    float c[4][8][4];
    #pragma unroll
    for (int a = 0; a < 4; a++)
        #pragma unroll
        for (int b = 0; b < 8; b++)
            #pragma unroll
            for (int k = 0; k < 4; k++) c[a][b][k] = 0.f;

    for (int i = 0; i < NC; i++){
        asm volatile("cp.async.wait_group %0;" :: "n"(S-2) : "memory");
        __syncthreads();
        if (i + S - 1 < NC) stage(i + S - 1, (i + S - 1) & (S - 1));
        asm volatile("cp.async.commit_group;" ::: "memory");

        const uint32_t Abase = As0 + (i & (S-1)) * ABYTES + aoff;
        const uint32_t Bbase = Bs0 + (i & (S-1)) * BBYTES + boff;
        #pragma unroll
        for (int ks = 0; ks < 2; ks++){
            uint32_t af[4][4], bf[4][4];
            #pragma unroll
            for (int mt = 0; mt < 4; mt++)
                ldsm4(af[mt], Abase + mt * (16 * ASTRB) + ks * 32);
            #pragma unroll
            for (int nt = 0; nt < 4; nt++)
                ldsm4t(bf[nt], Bbase + ks * (16 * BSTRB) + nt * 32);
            #pragma unroll
            for (int mt = 0; mt < 4; mt++)
                #pragma unroll
                for (int nt = 0; nt < 4; nt++){
                    mma_f16(c[mt][2*nt],   af[mt], bf[nt]);
                    mma_f16(c[mt][2*nt+1], af[mt], bf[nt] + 2);
                }
        }
    }

    // ---------------- epilogue ----------------
    #pragma unroll
    for (int mt = 0; mt < 4; mt++){
        const int r0l = wm + mt * 16 + gq;
        const int r1l = r0l + 8;
        const bool v0 = (m0 + r0l) < rows;
        const bool v1 = (m0 + r1l) < rows;
        const size_t gr0 = (size_t)(start + m0 + (v0 ? r0l : 0));
        const size_t gr1 = (size_t)(start + m0 + (v1 ? r1l : 0));
        float pw0 = 0.f, pw1 = 0.f;
        if (PHASE == 2){
            pw0 = v0 ? g_pw[gr0] : 0.f;
            pw1 = v1 ? g_pw[gr1] : 0.f;
        }
        #pragma unroll
        for (int j = 0; j < 8; j++){
            const int nw = (j >> 1) * 16 + (j & 1) * 8;
            const int n = wn + nw + 2 * tq;
            const float bb0 = bias_s[n], bb1 = bias_s[n + 1];
            float v00 = c[mt][j][0] + bb0, v01 = c[mt][j][1] + bb1;
            float v10 = c[mt][j][2] + bb0, v11 = c[mt][j][3] + bb1;
            if (PHASE == 1){
                if (v0)
                    *(__half2*)(g_hmidh + gr0 * ND + n0 + n) =
                        __floats2half2_rn(fmaxf(v00, 0.f), fmaxf(v01, 0.f));
                if (v1)
                    *(__half2*)(g_hmidh + gr1 * ND + n0 + n) =
                        __floats2half2_rn(fmaxf(v10, 0.f), fmaxf(v11, 0.f));
            } else {
                if (v0)
                    *(__half2*)(g_yh + gr0 * ND + n0 + n) =
                        __floats2half2_rn(v00 * pw0, v01 * pw0);
                if (v1)
                    *(__half2*)(g_yh + gr1 * ND + n0 + n) =
                        __floats2half2_rn(v10 * pw1, v11 * pw1);
            }
        }
    }
}

// ---------------- combine: out[t] = Y[pos(t,0)] + Y[pos(t,1)] ----------------
__global__ __launch_bounds__(256) void combine_kernel(float* __restrict__ out){
    size_t idx = (size_t)blockIdx.x * 256 + threadIdx.x;   // one float4 (4 outs)
    int t = (int)(idx >> 8);
    int j = (int)(idx & 255);
    int p0 = g_pos[2 * t], p1 = g_pos[2 * t + 1];
    const __half2* a2 = (const __half2*)(g_yh + (size_t)p0 * HD) + 2 * j;
    const __half2* b2 = (const __half2*)(g_yh + (size_t)p1 * HD) + 2 * j;
    float2 a0 = __half22float2(a2[0]), a1 = __half22float2(a2[1]);
    float2 c0 = __half22float2(b2[0]), c1 = __half22float2(b2[1]);
    ((float4*)out)[idx] = make_float4(a0.x + c0.x, a0.y + c0.y,
                                      a1.x + c1.x, a1.y + c1.y);
}

// ---------------- launch ----------------
extern "C" void kernel_launch(void* const* d_in, const int* in_sizes, int n_in,
                              void* d_out, int out_size) {
    const float* X  = (const float*)d_in[0];
    const float* Wg = (const float*)d_in[1];
    const float* bg = (const float*)d_in[2];
    const float* W1 = (const float*)d_in[3];
    const float* b1 = (const float*)d_in[4];
    const float* W2 = (const float*)d_in[5];
    const float* b2 = (const float*)d_in[6];
    float* out = (float*)d_out;

    // one-time host-side resources (created on the uncaptured correctness call;
    // capture sees only the fork/join edges)
    static cudaStream_t s2 = nullptr;
    static cudaEvent_t evFork = nullptr, evW1 = nullptr, evW2 = nullptr;
    if (!s2){
        cudaStreamCreateWithFlags(&s2, cudaStreamNonBlocking);
        cudaEventCreateWithFlags(&evFork, cudaEventDisableTiming);
        cudaEventCreateWithFlags(&evW1,  cudaEventDisableTiming);
        cudaEventCreateWithFlags(&evW2,  cudaEventDisableTiming);
        cudaFuncSetAttribute(gate_kernel,
                             cudaFuncAttributeMaxDynamicSharedMemorySize, GATE_SMEM);
        cudaFuncSetAttribute(moe_gemm_h<HD, MD, 1>,
                             cudaFuncAttributeMaxDynamicSharedMemorySize, GEMM_SMEM);
        cudaFuncSetAttribute(moe_gemm_h<MD, HD, 2>,
                             cudaFuncAttributeMaxDynamicSharedMemorySize, GEMM_SMEM);
    }

    __half* w1h; cudaGetSymbolAddress((void**)&w1h, g_w1h);
    __half* w2h; cudaGetSymbolAddress((void**)&w2h, g_w2h);

    // fork: weight conversions on side stream, overlapping the routing chain
    cudaEventRecord(evFork, 0);
    cudaStreamWaitEvent(s2, evFork, 0);
    cvt_half_kernel<<<(int)(((size_t)NE*HD*MD/4) / 256), 256, 0, s2>>>(W1, w1h);
    cudaEventRecord(evW1, s2);
    cvt_half_kernel<<<(int)(((size_t)NE*MD*HD/4) / 256), 256, 0, s2>>>(W2, w2h);
    cudaEventRecord(evW2, s2);

    // main stream: routing chain
    init_kernel<<<1, 32>>>();
    gate_kernel<<<TOK / 128, 256, GATE_SMEM>>>(X, Wg, bg);
    scan_kernel<<<1, 32>>>();
    scatter_kernel<<<RT / 256, 256>>>();

    // join W1, run phase 1 (W2 conversion may still be in flight)
    cudaStreamWaitEvent(0, evW1, 0);
    moe_gemm_h<HD, MD, 1><<<dim3(MD / 256, RT / 128, NE), 256, GEMM_SMEM>>>(b1);

    // join W2, run phase 2
    cudaStreamWaitEvent(0, evW2, 0);
    moe_gemm_h<MD, HD, 2><<<dim3(HD / 256, RT / 128, NE), 256, GEMM_SMEM>>>(b2);

    combine_kernel<<<TOK * HD / 1024, 256>>>(out);
}

// round 14
// speedup vs baseline: 1.2873x; 1.0108x over previous
#include <cuda_runtime.h>
#include <cuda_fp16.h>
#include <cstdint>
#include <cstddef>

#define TOK 16384
#define HD 1024
#define MD 2048
#define NE 16
#define RT (TOK*2)

// ---------------- scratch (device globals: allocation-free) ----------------
__device__ int    g_cnt[NE];
__device__ int    g_cur[NE];
__device__ int    g_offs[NE+1];
__device__ int    g_texp[RT];
__device__ float  g_tw[RT];
__device__ int    g_ptok[RT];
__device__ float  g_pw[RT];
__device__ int    g_pos[RT];
__device__ __half g_xah [(size_t)TOK * HD];     // fp16 X, token-indexed (34MB)
__device__ __half g_w1h [(size_t)NE * HD * MD]; // W1 fp16, original [e][k][n] layout
__device__ __half g_w2h [(size_t)NE * MD * HD]; // W2 fp16, original [e][k][n] layout
__device__ __half g_hmidh[(size_t)RT * MD];     // intermediate, fp16 (134MB)
__device__ __half g_yh  [(size_t)RT * HD];      // per-(token,expert) outputs fp16 (67MB)

// ---------------- helpers ----------------
__device__ __forceinline__ uint32_t smem_u32(const void* p){
    uint32_t a;
    asm("{ .reg .u64 t; cvta.to.shared.u64 t, %1; cvt.u32.u64 %0, t; }" : "=r"(a) : "l"(p));
    return a;
}
__device__ __forceinline__ void cpa16(uint32_t dst, const void* src, bool valid){
    asm volatile("cp.async.cg.shared.global [%0], [%1], 16, %2;\n"
                 :: "r"(dst), "l"(src), "r"(valid ? 16 : 0) : "memory");
}
__device__ __forceinline__ void ldsm4(uint32_t* r, uint32_t addr){
    asm volatile("ldmatrix.sync.aligned.m8n8.x4.shared.b16 {%0,%1,%2,%3}, [%4];"
                 : "=r"(r[0]), "=r"(r[1]), "=r"(r[2]), "=r"(r[3]) : "r"(addr));
}
__device__ __forceinline__ void ldsm4t(uint32_t* r, uint32_t addr){
    asm volatile("ldmatrix.sync.aligned.m8n8.x4.trans.shared.b16 {%0,%1,%2,%3}, [%4];"
                 : "=r"(r[0]), "=r"(r[1]), "=r"(r[2]), "=r"(r[3]) : "r"(addr));
}
__device__ __forceinline__ void mma_f16(float* c, const uint32_t* a, const uint32_t* b){
    asm volatile("mma.sync.aligned.m16n8k16.row.col.f32.f16.f16.f32 "
        "{%0,%1,%2,%3}, {%4,%5,%6,%7}, {%8,%9}, {%0,%1,%2,%3};"
        : "+f"(c[0]), "+f"(c[1]), "+f"(c[2]), "+f"(c[3])
        : "r"(a[0]), "r"(a[1]), "r"(a[2]), "r"(a[3]), "r"(b[0]), "r"(b[1]));
}

// ---------------- routing kernels ----------------
__global__ void init_kernel(){
    int i = threadIdx.x;
    if (i < NE){ g_cnt[i] = 0; g_cur[i] = 0; }
}

// gate: 64 tokens/block, 256 threads, 4 threads per token (quarter of each
// 64-wide H chunk each). Wg resident in SMEM (broadcast reads), X staged in
// SMEM; emits fp16 X (token-indexed) as a side product.
static constexpr int GATE_SMEM = 1024*16*4 + 64*68*4 + 64*48*4 + 64;  // 95296
__global__ __launch_bounds__(256)
void gate_kernel(const float* __restrict__ X,
                 const float* __restrict__ Wg, const float* __restrict__ bg){
    extern __shared__ float gsm[];
    float* sWg  = gsm;                      // [1024][16]
    float* sX   = gsm + 1024*16;            // [64][68] (stride 68)
    float* sRed = gsm + 1024*16 + 64*68;    // [64][48] partials (quarters 1..3)
    int*   scnt = (int*)(sRed + 64*48);

    const int tid   = threadIdx.x;
    const int token = tid & 63;
    const int quart = tid >> 6;             // 0..3: 16-wide slice of each chunk
    const int t0    = blockIdx.x * 64;

    if (tid < NE) scnt[tid] = 0;
    // preload Wg (16384 floats = 4096 float4, 16 per thread)
    #pragma unroll
    for (int i = 0; i < 16; i++){
        int f = i * 256 + tid;
        *(float4*)&sWg[f * 4] = ((const float4*)Wg)[f];
    }

    float acc[NE];
    #pragma unroll
    for (int e = 0; e < NE; e++) acc[e] = 0.f;

    for (int hb = 0; hb < HD; hb += 64){
        __syncthreads();
        // stage X[64][64] coalesced (1024 float4, 4 per thread) + emit fp16
        #pragma unroll
        for (int i = 0; i < 4; i++){
            int f = i * 256 + tid;
            int row = f >> 4, c4 = (f & 15) * 4;
            float4 v = *(const float4*)(X + (size_t)(t0 + row) * HD + hb + c4);
            *(float4*)&sX[row * 68 + c4] = v;
            __half2 h0 = __floats2half2_rn(v.x, v.y);
            __half2 h1 = __floats2half2_rn(v.z, v.w);
            __half2* dst = (__half2*)(g_xah + (size_t)(t0 + row) * HD + hb + c4);
            dst[0] = h0; dst[1] = h1;
        }
        __syncthreads();
        // compute: this thread's 16-wide slice of the 64-chunk
        const int hoff = quart * 16;
        #pragma unroll
        for (int h4 = 0; h4 < 16; h4 += 4){
            float4 x = *(const float4*)&sX[token * 68 + hoff + h4];
            const float xs[4] = {x.x, x.y, x.z, x.w};
            #pragma unroll
            for (int j = 0; j < 4; j++){
                const float4* w4 = (const float4*)&sWg[(hb + hoff + h4 + j) * 16];
                float xv = xs[j];
                #pragma unroll
                for (int q = 0; q < 4; q++){
                    float4 w = w4[q];
                    acc[4*q+0] += xv * w.x; acc[4*q+1] += xv * w.y;
                    acc[4*q+2] += xv * w.z; acc[4*q+3] += xv * w.w;
                }
            }
        }
    }

    // quarter reduction: quarters 1..3 deposit, quarter 0 combines + finalizes
    __syncthreads();
    if (quart != 0){
        #pragma unroll
        for (int e = 0; e < NE; e++) sRed[token * 48 + (quart - 1) * 16 + e] = acc[e];
    }
    __syncthreads();
    if (quart == 0){
        #pragma unroll
        for (int e = 0; e < NE; e++)
            acc[e] += sRed[token * 48 + e] + sRed[token * 48 + 16 + e]
                    + sRed[token * 48 + 32 + e] + bg[e];
        int i1 = 0;
        #pragma unroll
        for (int e = 1; e < NE; e++) if (acc[e] > acc[i1]) i1 = e;
        int i2 = (i1 == 0) ? 1 : 0;
        #pragma unroll
        for (int e = 0; e < NE; e++) if (e != i1 && acc[e] > acc[i2]) i2 = e;
        float w1 = 1.f / (1.f + expf(acc[i2] - acc[i1]));
        float w2 = 1.f - w1;
        const int t = t0 + token;
        g_texp[2*t]   = i1; g_tw[2*t]   = w1;
        g_texp[2*t+1] = i2; g_tw[2*t+1] = w2;
        atomicAdd(&scnt[i1], 1); atomicAdd(&scnt[i2], 1);
    }
    __syncthreads();
    if (tid < NE) atomicAdd(&g_cnt[tid], scnt[tid]);
}

__global__ void scan_kernel(){
    if (threadIdx.x == 0){
        int s = 0;
        for (int e = 0; e < NE; e++){ g_offs[e] = s; s += g_cnt[e]; }
        g_offs[NE] = s;
    }
}

__global__ __launch_bounds__(256) void scatter_kernel(){
    int i = blockIdx.x * 256 + threadIdx.x;
    int e = g_texp[i];
    int p = g_offs[e] + atomicAdd(&g_cur[e], 1);
    g_ptok[p] = i >> 1;
    g_pw[p]   = g_tw[i];
    g_pos[i]  = p;
}

// ---------------- pre-pass: fp32 -> fp16 weights ----------------
__global__ __launch_bounds__(256) void cvt_half_kernel(const float* __restrict__ src,
                                                       __half* __restrict__ dst){
    size_t i = (size_t)blockIdx.x * 256 + threadIdx.x;   // one float4 per thread
    float4 v = ((const float4*)src)[i];
    __half2* d2 = (__half2*)dst;
    d2[2*i]   = __floats2half2_rn(v.x, v.y);
    d2[2*i+1] = __floats2half2_rn(v.z, v.w);
}

// ---------------- fp16 grouped GEMM, BK=32, 4-stage cp.async pipeline -------
// PHASE 1: hmid[p,:] = f16(relu(xah[tok(p),:] @ W1[e] + b1[e]))  (KD=HD, ND=MD)
// PHASE 2: yh[p,:]   = f16(pw(p) * (hmid[p,:] @ W2[e] + b2[e]))  (KD=MD, ND=HD)
static constexpr int GEMM_SMEM = 1024 + 4*(128*40*2) + 4*(32*264*2);  // 109568

template<int KD, int ND, int PHASE>
__global__ __launch_bounds__(256, 1)
void moe_gemm_h(const float* __restrict__ bias)
{
    constexpr int BM = 128, BN = 256, BK = 32, S = 4;
    constexpr int NC = KD / BK;
    constexpr int ASTRB = 80;     // bytes per A SMEM row (32 halves + 8 pad)
    constexpr int BSTRB = 528;    // bytes per B SMEM row (256 halves + 8 pad)
    constexpr int ABYTES = BM * ASTRB;   // 10240
    constexpr int BBYTES = BK * BSTRB;   // 16896
    extern __shared__ char smem[];
    float* bias_s = (float*)smem;
    const uint32_t As0 = smem_u32(smem + 1024);
    const uint32_t Bs0 = As0 + S * ABYTES;

    const int e = blockIdx.z;
    const int start = g_offs[e];
    const int rows  = g_offs[e+1] - start;
    const int m0 = blockIdx.y * BM;
    if (m0 >= rows) return;
    const int n0 = blockIdx.x * BN;
    const int tid = threadIdx.x, wid = tid >> 5, lane = tid & 31;

    const __half* Ab = (PHASE == 1) ? (const __half*)g_xah : (const __half*)g_hmidh;
    const __half* Wh = (PHASE == 1) ? (const __half*)g_w1h : (const __half*)g_w2h;

    bias_s[tid] = bias[(size_t)e * ND + n0 + tid];

    // staging assignment (phase 1: A rows via token indirection)
    const int ar = tid >> 1, ac = tid & 1;          // A: row, 32B-half
    const bool a_ok = (m0 + ar) < rows;
    size_t arow;
    if (PHASE == 1) arow = (size_t)g_ptok[start + m0 + (a_ok ? ar : 0)];
    else            arow = (size_t)(start + m0 + (a_ok ? ar : 0));
    const __half* a_srcrow = Ab + arow * KD + ac * 16;
    const uint32_t a_doff = (uint32_t)(ar * ASTRB + ac * 32);
    const int br = tid >> 3, bc = tid & 7;          // B: k-row, 64B col chunk
    const __half* b_srcrow = Wh + ((size_t)e * KD + br) * ND + n0 + bc * 32;
    const uint32_t b_doff = (uint32_t)(br * BSTRB + bc * 64);

    auto stage = [&](int c, int slot){
        uint32_t Abase = As0 + slot * ABYTES;
        uint32_t Bbase = Bs0 + slot * BBYTES;
        const __half* as = a_srcrow + c * BK;
        cpa16(Abase + a_doff,      as,     a_ok);
        cpa16(Abase + a_doff + 16, as + 8, a_ok);
        const __half* bs = b_srcrow + (size_t)c * BK * ND;
        #pragma unroll
        for (int j = 0; j < 4; j++) cpa16(Bbase + b_doff + j*16, bs + j*8, true);
    };

    // prologue: stages 0..S-2
    #pragma unroll
    for (int i = 0; i < S-1; i++){
        stage(i, i);
        asm volatile("cp.async.commit_group;" ::: "memory");
    }

    // per-lane fragment addressing
    const int wm = (wid & 1) * 64, wn = (wid >> 1) * 64;
    const int g = lane >> 3, lr = lane & 7, gq = lane >> 2, tq = lane & 3;
    const uint32_t aoff = (uint32_t)((wm + (g & 1) * 8 + lr) * ASTRB + (g >> 1) * 16);
    const uint32_t boff = (uint32_t)(((g & 1) * 8 + lr) * BSTRB + (g >> 1) * 16 + wn * 2);

    float c[4][8][4];
    #pragma unroll
    for (int a = 0; a < 4; a++)
        #pragma unroll
        for (int b = 0; b < 8; b++)
            #pragma unroll
            for (int k = 0; k < 4; k++) c[a][b][k] = 0.f;

    for (int i = 0; i < NC; i++){
        asm volatile("cp.async.wait_group %0;" :: "n"(S-2) : "memory");
        __syncthreads();
        if (i + S - 1 < NC) stage(i + S - 1, (i + S - 1) & (S - 1));
        asm volatile("cp.async.commit_group;" ::: "memory");

        const uint32_t Abase = As0 + (i & (S-1)) * ABYTES + aoff;
        const uint32_t Bbase = Bs0 + (i & (S-1)) * BBYTES + boff;
        #pragma unroll
        for (int ks = 0; ks < 2; ks++){
            uint32_t af[4][4], bf[4][4];
            #pragma unroll
            for (int mt = 0; mt < 4; mt++)
                ldsm4(af[mt], Abase + mt * (16 * ASTRB) + ks * 32);
            #pragma unroll
            for (int nt = 0; nt < 4; nt++)
                ldsm4t(bf[nt], Bbase + ks * (16 * BSTRB) + nt * 32);
            #pragma unroll
            for (int mt = 0; mt < 4; mt++)
                #pragma unroll
                for (int nt = 0; nt < 4; nt++){
                    mma_f16(c[mt][2*nt],   af[mt], bf[nt]);
                    mma_f16(c[mt][2*nt+1], af[mt], bf[nt] + 2);
                }
        }
    }

    // ---------------- epilogue ----------------
    #pragma unroll
    for (int mt = 0; mt < 4; mt++){
        const int r0l = wm + mt * 16 + gq;
        const int r1l = r0l + 8;
        const bool v0 = (m0 + r0l) < rows;
        const bool v1 = (m0 + r1l) < rows;
        const size_t gr0 = (size_t)(start + m0 + (v0 ? r0l : 0));
        const size_t gr1 = (size_t)(start + m0 + (v1 ? r1l : 0));
        float pw0 = 0.f, pw1 = 0.f;
        if (PHASE == 2){
            pw0 = v0 ? g_pw[gr0] : 0.f;
            pw1 = v1 ? g_pw[gr1] : 0.f;
        }
        #pragma unroll
        for (int j = 0; j < 8; j++){
            const int nw = (j >> 1) * 16 + (j & 1) * 8;
            const int n = wn + nw + 2 * tq;
            const float bb0 = bias_s[n], bb1 = bias_s[n + 1];
            float v00 = c[mt][j][0] + bb0, v01 = c[mt][j][1] + bb1;
            float v10 = c[mt][j][2] + bb0, v11 = c[mt][j][3] + bb1;
            if (PHASE == 1){
                if (v0)
                    *(__half2*)(g_hmidh + gr0 * ND + n0 + n) =
                        __floats2half2_rn(fmaxf(v00, 0.f), fmaxf(v01, 0.f));
                if (v1)
                    *(__half2*)(g_hmidh + gr1 * ND + n0 + n) =
                        __floats2half2_rn(fmaxf(v10, 0.f), fmaxf(v11, 0.f));
            } else {
                if (v0)
                    *(__half2*)(g_yh + gr0 * ND + n0 + n) =
                        __floats2half2_rn(v00 * pw0, v01 * pw0);
                if (v1)
                    *(__half2*)(g_yh + gr1 * ND + n0 + n) =
                        __floats2half2_rn(v10 * pw1, v11 * pw1);
            }
        }
    }
}

// ---------------- combine: out[t] = Y[pos(t,0)] + Y[pos(t,1)] ----------------
__global__ __launch_bounds__(256) void combine_kernel(float* __restrict__ out){
    size_t idx = (size_t)blockIdx.x * 256 + threadIdx.x;   // one float4 (4 outs)
    int t = (int)(idx >> 8);
    int j = (int)(idx & 255);
    int p0 = g_pos[2 * t], p1 = g_pos[2 * t + 1];
    const __half2* a2 = (const __half2*)(g_yh + (size_t)p0 * HD) + 2 * j;
    const __half2* b2 = (const __half2*)(g_yh + (size_t)p1 * HD) + 2 * j;
    float2 a0 = __half22float2(a2[0]), a1 = __half22float2(a2[1]);
    float2 c0 = __half22float2(b2[0]), c1 = __half22float2(b2[1]);
    ((float4*)out)[idx] = make_float4(a0.x + c0.x, a0.y + c0.y,
                                      a1.x + c1.x, a1.y + c1.y);
}

// ---------------- launch ----------------
extern "C" void kernel_launch(void* const* d_in, const int* in_sizes, int n_in,
                              void* d_out, int out_size) {
    const float* X  = (const float*)d_in[0];
    const float* Wg = (const float*)d_in[1];
    const float* bg = (const float*)d_in[2];
    const float* W1 = (const float*)d_in[3];
    const float* b1 = (const float*)d_in[4];
    const float* W2 = (const float*)d_in[5];
    const float* b2 = (const float*)d_in[6];
    float* out = (float*)d_out;

    // one-time host-side resources (created on the uncaptured correctness call;
    // capture sees only the fork/join edges)
    static cudaStream_t s2 = nullptr;
    static cudaEvent_t evFork = nullptr, evW1 = nullptr, evW2 = nullptr;
    if (!s2){
        cudaStreamCreateWithFlags(&s2, cudaStreamNonBlocking);
        cudaEventCreateWithFlags(&evFork, cudaEventDisableTiming);
        cudaEventCreateWithFlags(&evW1,  cudaEventDisableTiming);
        cudaEventCreateWithFlags(&evW2,  cudaEventDisableTiming);
        cudaFuncSetAttribute(gate_kernel,
                             cudaFuncAttributeMaxDynamicSharedMemorySize, GATE_SMEM);
        cudaFuncSetAttribute(moe_gemm_h<HD, MD, 1>,
                             cudaFuncAttributeMaxDynamicSharedMemorySize, GEMM_SMEM);
        cudaFuncSetAttribute(moe_gemm_h<MD, HD, 2>,
                             cudaFuncAttributeMaxDynamicSharedMemorySize, GEMM_SMEM);
    }

    __half* w1h; cudaGetSymbolAddress((void**)&w1h, g_w1h);
    __half* w2h; cudaGetSymbolAddress((void**)&w2h, g_w2h);

    // fork: weight conversions on side stream, overlapping the routing chain
    cudaEventRecord(evFork, 0);
    cudaStreamWaitEvent(s2, evFork, 0);
    cvt_half_kernel<<<(int)(((size_t)NE*HD*MD/4) / 256), 256, 0, s2>>>(W1, w1h);
    cudaEventRecord(evW1, s2);
    cvt_half_kernel<<<(int)(((size_t)NE*MD*HD/4) / 256), 256, 0, s2>>>(W2, w2h);
    cudaEventRecord(evW2, s2);

    // main stream: routing chain
    init_kernel<<<1, 32>>>();
    gate_kernel<<<TOK / 64, 256, GATE_SMEM>>>(X, Wg, bg);
    scan_kernel<<<1, 32>>>();
    scatter_kernel<<<RT / 256, 256>>>();

    // join W1, run phase 1 (W2 conversion may still be in flight)
    cudaStreamWaitEvent(0, evW1, 0);
    moe_gemm_h<HD, MD, 1><<<dim3(MD / 256, RT / 128, NE), 256, GEMM_SMEM>>>(b1);

    // join W2, run phase 2
    cudaStreamWaitEvent(0, evW2, 0);
    moe_gemm_h<MD, HD, 2><<<dim3(HD / 256, RT / 128, NE), 256, GEMM_SMEM>>>(b2);

    combine_kernel<<<TOK * HD / 1024, 256>>>(out);
}